// round 5
// baseline (speedup 1.0000x reference)
#include <cuda_runtime.h>
#include <math.h>

#define T_SEQ 512
#define NB    64
#define NI    256
#define NH    512

// Scratch: input projection result (64 MB) + barrier tree.
__device__ float    g_pre[(size_t)T_SEQ * NB * NH];
__device__ unsigned g_leaf[8 * 64];   // 8 counters, 256 B apart (distinct LTS)
__device__ unsigned g_root;
__device__ unsigned g_flag;

__global__ void reset_bar() {
    if (threadIdx.x < 8) g_leaf[threadIdx.x * 64] = 0u;
    if (threadIdx.x == 0) { g_root = 0u; g_flag = 0u; }
}

typedef unsigned long long ull;

// Packed 2x fp32 FMA (sm_10x f32x2 pipe): d = a*b + c elementwise on pairs.
#define FFMA2(d, a, b, c) \
    asm("fma.rn.f32x2 %0, %1, %2, %3;" : "=l"(d) : "l"(a), "l"(b), "l"(c))

__device__ __forceinline__ ull pack2(float lo, float hi) {
    ull r;
    asm("mov.b64 %0, {%1, %2};"
        : "=l"(r) : "r"(__float_as_uint(lo)), "r"(__float_as_uint(hi)));
    return r;
}
__device__ __forceinline__ float2 unpack2(ull v) {
    unsigned lo, hi;
    asm("mov.b64 {%0, %1}, %2;" : "=r"(lo), "=r"(hi) : "l"(v));
    return make_float2(__uint_as_float(lo), __uint_as_float(hi));
}

// ---------------------------------------------------------------------------
// GEMM: g_pre[m][j] = sum_k x[m][k] * W_ih[j][k] + b_ih[j] + b_hh[j]
// M = T*B = 32768, N = 512, K = 256.  BM=128, BN=64, BK=16, 256 thr, 8x4 micro.
// ---------------------------------------------------------------------------
#define BM 128
#define BN 64
#define BK 16

__global__ __launch_bounds__(256) void gemm_xw(
    const float* __restrict__ A,    // [M][256]
    const float* __restrict__ Wih,  // [512][256]
    const float* __restrict__ bih,
    const float* __restrict__ bhh)
{
    __shared__ float As[BK][BM + 4];
    __shared__ float Bs[BK][BN + 4];
    const int m0 = blockIdx.y * BM;
    const int n0 = blockIdx.x * BN;
    const int tid = threadIdx.x;
    const int ty = tid >> 4;   // 0..15 -> 8 rows each
    const int tx = tid & 15;   // 0..15 -> 4 cols each

    ull acc2[8][2];
#pragma unroll
    for (int i = 0; i < 8; ++i) { acc2[i][0] = 0ull; acc2[i][1] = 0ull; }

    for (int k0 = 0; k0 < NI; k0 += BK) {
        // A tile (128x16) -> As[k][m]
#pragma unroll
        for (int i = 0; i < 2; ++i) {
            int f  = tid + i * 256;       // 0..511 float4s
            int r  = f >> 2;              // row 0..127
            int c4 = f & 3;               // float4 within 16-wide k slab
            float4 v = *(const float4*)(A + (size_t)(m0 + r) * NI + k0 + c4 * 4);
            As[c4 * 4 + 0][r] = v.x;
            As[c4 * 4 + 1][r] = v.y;
            As[c4 * 4 + 2][r] = v.z;
            As[c4 * 4 + 3][r] = v.w;
        }
        // B tile (64x16) -> Bs[k][n]
        {
            int r  = tid >> 2;
            int c4 = tid & 3;
            float4 v = *(const float4*)(Wih + (size_t)(n0 + r) * NI + k0 + c4 * 4);
            Bs[c4 * 4 + 0][r] = v.x;
            Bs[c4 * 4 + 1][r] = v.y;
            Bs[c4 * 4 + 2][r] = v.z;
            Bs[c4 * 4 + 3][r] = v.w;
        }
        __syncthreads();
#pragma unroll
        for (int k = 0; k < BK; ++k) {
            float a[8];
            *(float4*)&a[0] = *(const float4*)&As[k][ty * 8];
            *(float4*)&a[4] = *(const float4*)&As[k][ty * 8 + 4];
            ulonglong2 b2 = *(const ulonglong2*)&Bs[k][tx * 4];
#pragma unroll
            for (int i = 0; i < 8; ++i) {
                ull aa = pack2(a[i], a[i]);
                FFMA2(acc2[i][0], aa, b2.x, acc2[i][0]);
                FFMA2(acc2[i][1], aa, b2.y, acc2[i][1]);
            }
        }
        __syncthreads();
    }

    const int n = n0 + tx * 4;
    float4 bias = make_float4(bih[n + 0] + bhh[n + 0], bih[n + 1] + bhh[n + 1],
                              bih[n + 2] + bhh[n + 2], bih[n + 3] + bhh[n + 3]);
#pragma unroll
    for (int i = 0; i < 8; ++i) {
        float2 p0 = unpack2(acc2[i][0]);
        float2 p1 = unpack2(acc2[i][1]);
        float4 o;
        o.x = p0.x + bias.x;
        o.y = p0.y + bias.y;
        o.z = p1.x + bias.z;
        o.w = p1.y + bias.w;
        *(float4*)(g_pre + (size_t)(m0 + ty * 8 + i) * NH + n) = o;
    }
}

// ---------------------------------------------------------------------------
// Persistent recurrence kernel: 128 CTAs (16 j-tiles x 8 b-tiles), 256 thr.
// Thread (lane=j, warp=k-slice of 64) holds W_hh[j][kslice] in 64 registers.
// Grid barrier: 2-level atomic tree (8 leaves -> root -> release flag),
// release/acquire ordering carried on the atomics (no full threadfence).
// ---------------------------------------------------------------------------
#define RG 128
#define RT 256

__global__ __launch_bounds__(RT, 1) void rnn_recur(
    const float* __restrict__ h0,    // [B][H]
    const float* __restrict__ Whh,   // [H][H]
    float* __restrict__ hseq,        // [T][B][H]
    float* __restrict__ hlast)       // [B][H] or nullptr
{
    __shared__ float hs[8 * NH];          // staged h_{t-1} tile (16 KB)
    __shared__ float part[8 * 8 * 32];    // partials [warp][b][lane] (8 KB)

    const int jt   = blockIdx.x & 15;
    const int bt   = blockIdx.x >> 4;
    const int j0   = jt * 32;
    const int b0   = bt * 8;
    const int lane = threadIdx.x & 31;
    const int warp = threadIdx.x >> 5;
    const int j    = j0 + lane;           // output column this thread owns
    const int k0   = warp * 64;           // k-slice this warp owns
    const int leaf = blockIdx.x & 7;      // leaf counter assignment (16 CTAs each)

    // W_hh[j][k0 .. k0+63] -> 32 packed-pair registers (lives whole kernel).
    ull w2[32];
    {
        const ulonglong2* wp = (const ulonglong2*)(Whh + (size_t)j * NH + k0);
#pragma unroll
        for (int c = 0; c < 16; ++c) {
            ulonglong2 v = __ldg(wp + c);
            w2[2 * c]     = v.x;
            w2[2 * c + 1] = v.y;
        }
    }

    const float* hprev = h0;

    for (int t = 0; t < T_SEQ; ++t) {
        // Prefetch this thread's pre-activation (independent of h).
        float pre = __ldcg(g_pre + ((size_t)t * NB + (b0 + warp)) * NH + j);

        // Stage h_{t-1} tile (8 x 512 floats) L2 -> smem.
#pragma unroll
        for (int r = 0; r < 4; ++r) {
            int idx = threadIdx.x + r * RT;   // 0..1023 float4 slots
            int row = idx >> 7;
            int c4  = idx & 127;
            *(float4*)(hs + row * NH + c4 * 4) =
                __ldcg((const float4*)(hprev + (size_t)(b0 + row) * NH + c4 * 4));
        }
        __syncthreads();

        // 8 partial dot products (one per batch), K-slice of 64, packed FMAs.
        float accs[8];
#pragma unroll
        for (int b = 0; b < 8; ++b) {
            const ulonglong2* hp = (const ulonglong2*)(hs + b * NH + k0);
            ull a0 = 0ull, a1 = 0ull;
#pragma unroll
            for (int c = 0; c < 16; ++c) {
                ulonglong2 hv = hp[c];   // broadcast LDS.128
                FFMA2(a0, w2[2 * c],     hv.x, a0);
                FFMA2(a1, w2[2 * c + 1], hv.y, a1);
            }
            float2 f0 = unpack2(a0);
            float2 f1 = unpack2(a1);
            accs[b] = (f0.x + f0.y) + (f1.x + f1.y);
        }

        // Cross-warp reduction: part[warp][b][lane], conflict-free both ways.
#pragma unroll
        for (int b = 0; b < 8; ++b)
            part[warp * 256 + b * 32 + lane] = accs[b];
        __syncthreads();

        float s = 0.f;
#pragma unroll
        for (int w = 0; w < 8; ++w)
            s += part[w * 256 + warp * 32 + lane];

        const float hv = tanhf(s + pre);
        const int   bo = b0 + warp;
        hseq[((size_t)t * NB + bo) * NH + j] = hv;
        if (t == T_SEQ - 1 && hlast) hlast[(size_t)bo * NH + j] = hv;

        // --- Grid barrier: 2-level tree, release/acquire on the atomics. ---
        __syncthreads();   // all CTA stores done before thread 0 releases
        if (threadIdx.x == 0) {
            unsigned old;
            // Leaf arrival (release: orders this CTA's h stores; acquire so
            // the leaf-completer inherits visibility of its group's stores).
            asm volatile("atom.acq_rel.gpu.add.u32 %0, [%1], 1;"
                         : "=r"(old) : "l"(&g_leaf[leaf * 64]) : "memory");
            if (old == 16u * (unsigned)(t + 1) - 1u) {
                unsigned ro;
                asm volatile("atom.acq_rel.gpu.add.u32 %0, [%1], 1;"
                             : "=r"(ro) : "l"(&g_root) : "memory");
                if (ro == 8u * (unsigned)(t + 1) - 1u) {
                    asm volatile("st.release.gpu.u32 [%0], %1;"
                                 :: "l"(&g_flag), "r"((unsigned)(t + 1))
                                 : "memory");
                }
            }
            // Wait for release flag (acquire: orders subsequent h loads).
            unsigned f;
            do {
                asm volatile("ld.acquire.gpu.u32 %0, [%1];"
                             : "=r"(f) : "l"(&g_flag) : "memory");
            } while (f < (unsigned)(t + 1));
        }
        __syncthreads();   // propagate acquire to whole CTA

        hprev = hseq + (size_t)t * NB * NH;
    }
}

// ---------------------------------------------------------------------------
extern "C" void kernel_launch(void* const* d_in, const int* in_sizes, int n_in,
                              void* d_out, int out_size)
{
    const float* x   = (const float*)d_in[0];
    const float* h0  = (const float*)d_in[1];
    const float* Wih = (const float*)d_in[2];
    const float* Whh = (const float*)d_in[3];
    const float* bih = (const float*)d_in[4];
    const float* bhh = (const float*)d_in[5];
    float* out = (float*)d_out;

    float* hlast = nullptr;
    if (out_size >= (int)((size_t)T_SEQ * NB * NH + NB * NH))
        hlast = out + (size_t)T_SEQ * NB * NH;

    reset_bar<<<1, 32>>>();

    dim3 grid(NH / BN, (T_SEQ * NB) / BM);   // (8, 256)
    gemm_xw<<<grid, 256>>>(x, Wih, bih, bhh);

    rnn_recur<<<RG, RT>>>(h0, Whh, out, hlast);
}

// round 6
// speedup vs baseline: 1.1050x; 1.1050x over previous
#include <cuda_runtime.h>
#include <math.h>

#define T_SEQ 512
#define NB    64
#define NI    256
#define NH    512

// Scratch: input projection result (64 MB). Fits in L2 (126 MB) for re-read.
__device__ float g_pre[(size_t)T_SEQ * NB * NH];

typedef unsigned long long ull;

// Packed 2x fp32 FMA (sm_10x f32x2 pipe): d = a*b + c elementwise on pairs.
#define FFMA2(d, a, b, c) \
    asm("fma.rn.f32x2 %0, %1, %2, %3;" : "=l"(d) : "l"(a), "l"(b), "l"(c))

__device__ __forceinline__ ull pack2(float lo, float hi) {
    ull r;
    asm("mov.b64 %0, {%1, %2};"
        : "=l"(r) : "r"(__float_as_uint(lo)), "r"(__float_as_uint(hi)));
    return r;
}
__device__ __forceinline__ float2 unpack2(ull v) {
    unsigned lo, hi;
    asm("mov.b64 {%0, %1}, %2;" : "=r"(lo), "=r"(hi) : "l"(v));
    return make_float2(__uint_as_float(lo), __uint_as_float(hi));
}

// ---------------------------------------------------------------------------
// GEMM: g_pre[m][j] = sum_k x[m][k] * W_ih[j][k] + b_ih[j] + b_hh[j]
// M = T*B = 32768, N = 512, K = 256.  BM=128, BN=64, BK=16, 256 thr, 8x4 micro.
// ---------------------------------------------------------------------------
#define BM 128
#define BN 64
#define BK 16

__global__ __launch_bounds__(256) void gemm_xw(
    const float* __restrict__ A,    // [M][256]
    const float* __restrict__ Wih,  // [512][256]
    const float* __restrict__ bih,
    const float* __restrict__ bhh)
{
    __shared__ float As[BK][BM + 4];
    __shared__ float Bs[BK][BN + 4];
    const int m0 = blockIdx.y * BM;
    const int n0 = blockIdx.x * BN;
    const int tid = threadIdx.x;
    const int ty = tid >> 4;
    const int tx = tid & 15;

    ull acc2[8][2];
#pragma unroll
    for (int i = 0; i < 8; ++i) { acc2[i][0] = 0ull; acc2[i][1] = 0ull; }

    for (int k0 = 0; k0 < NI; k0 += BK) {
#pragma unroll
        for (int i = 0; i < 2; ++i) {
            int f  = tid + i * 256;
            int r  = f >> 2;
            int c4 = f & 3;
            float4 v = *(const float4*)(A + (size_t)(m0 + r) * NI + k0 + c4 * 4);
            As[c4 * 4 + 0][r] = v.x;
            As[c4 * 4 + 1][r] = v.y;
            As[c4 * 4 + 2][r] = v.z;
            As[c4 * 4 + 3][r] = v.w;
        }
        {
            int r  = tid >> 2;
            int c4 = tid & 3;
            float4 v = *(const float4*)(Wih + (size_t)(n0 + r) * NI + k0 + c4 * 4);
            Bs[c4 * 4 + 0][r] = v.x;
            Bs[c4 * 4 + 1][r] = v.y;
            Bs[c4 * 4 + 2][r] = v.z;
            Bs[c4 * 4 + 3][r] = v.w;
        }
        __syncthreads();
#pragma unroll
        for (int k = 0; k < BK; ++k) {
            float a[8];
            *(float4*)&a[0] = *(const float4*)&As[k][ty * 8];
            *(float4*)&a[4] = *(const float4*)&As[k][ty * 8 + 4];
            ulonglong2 b2 = *(const ulonglong2*)&Bs[k][tx * 4];
#pragma unroll
            for (int i = 0; i < 8; ++i) {
                ull aa = pack2(a[i], a[i]);
                FFMA2(acc2[i][0], aa, b2.x, acc2[i][0]);
                FFMA2(acc2[i][1], aa, b2.y, acc2[i][1]);
            }
        }
        __syncthreads();
    }

    const int n = n0 + tx * 4;
    float4 bias = make_float4(bih[n + 0] + bhh[n + 0], bih[n + 1] + bhh[n + 1],
                              bih[n + 2] + bhh[n + 2], bih[n + 3] + bhh[n + 3]);
#pragma unroll
    for (int i = 0; i < 8; ++i) {
        float2 p0 = unpack2(acc2[i][0]);
        float2 p1 = unpack2(acc2[i][1]);
        float4 o;
        o.x = p0.x + bias.x;
        o.y = p0.y + bias.y;
        o.z = p1.x + bias.z;
        o.w = p1.y + bias.w;
        *(float4*)(g_pre + (size_t)(m0 + ty * 8 + i) * NH + n) = o;
    }
}

// ---------------------------------------------------------------------------
// Recurrence: batches are INDEPENDENT -> no grid barrier. 16 clusters of 8
// CTAs; cluster g owns batches [4g, 4g+4), rank r owns columns [64r, 64r+64).
// h exchanged via DSMEM (st.shared::cluster) into a double-buffered smem
// tile; one barrier.cluster per step. W_hh slice lives in registers.
// Thread map (512 thr): warp w -> (kslice = w>>1 of 64 k, jhalf = w&1);
// thread owns column jj = jhalf*32+lane, accumulates 4 batch partials.
// ---------------------------------------------------------------------------
#define CL 8
#define RT 512

__global__ __launch_bounds__(RT, 1) __cluster_dims__(CL, 1, 1)
void rnn_recur(
    const float* __restrict__ h0,    // [B][H]
    const float* __restrict__ Whh,   // [H][H]
    float* __restrict__ hseq,        // [T][B][H]
    float* __restrict__ hlast)       // [B][H] or nullptr
{
    __shared__ float hbuf[2][4 * NH];     // double-buffered h tile (16 KB)
    __shared__ float part[8 * 4 * 64];    // partials [kslice][b][jj] (8 KB)
    __shared__ float hx[4 * 64];          // this CTA's fresh h chunk (1 KB)

    unsigned rank;
    asm("mov.u32 %0, %%cluster_ctarank;" : "=r"(rank));
    const int grp  = blockIdx.x >> 3;     // batch group 0..15
    const int b0   = grp * 4;
    const int j0   = (int)rank * 64;
    const int tid  = threadIdx.x;
    const int lane = tid & 31;
    const int warp = tid >> 5;
    const int ks   = warp >> 1;           // k-slice 0..7
    const int k0   = ks * 64;
    const int jj   = (warp & 1) * 32 + lane;   // column within CTA, 0..63
    const int j    = j0 + jj;

    // W_hh[j][k0..k0+63] -> 32 packed-pair registers.
    ull w2[32];
    {
        const ulonglong2* wp = (const ulonglong2*)(Whh + (size_t)j * NH + k0);
#pragma unroll
        for (int c = 0; c < 16; ++c) {
            ulonglong2 v = __ldg(wp + c);
            w2[2 * c]     = v.x;
            w2[2 * c + 1] = v.y;
        }
    }

    // Fill hbuf[0] with h0 rows b0..b0+3 (full H) — local only.
    {
        int row = tid >> 7;               // 512 float4 slots: row 0..3
        int c4  = tid & 127;
        *(float4*)&hbuf[0][row * NH + c4 * 4] =
            __ldg((const float4*)(h0 + (size_t)(b0 + row) * NH + c4 * 4));
    }
    asm volatile("barrier.cluster.arrive.aligned;" ::: "memory");
    asm volatile("barrier.cluster.wait.aligned;"   ::: "memory");

    // Exchange-store descriptors: thread sends one float4 to rank (tid>>6).
    const int dst_rank = tid >> 6;        // 0..7
    const int xidx     = tid & 63;        // float4 index 0..63
    const int xb       = xidx >> 4;       // batch 0..3
    const int xc4      = xidx & 15;       // float4 within 64-col chunk

    // Reducer map (warps 0..7): output (rb, rjl).
    const int rb  = warp >> 1;                 // 0..3 (valid for warp<8)
    const int rjl = (warp & 1) * 32 + lane;    // 0..63

    float pre = 0.f;
    if (warp < 8)
        pre = __ldg(g_pre + ((size_t)0 * NB + (b0 + rb)) * NH + j0 + rjl);

    for (int t = 0; t < T_SEQ; ++t) {
        const float* cur = hbuf[t & 1];

        // Partial dots: 4 batches x 64-k slice, packed FMAs, broadcast LDS.
        float accs[4];
#pragma unroll
        for (int b = 0; b < 4; ++b) {
            const ulonglong2* hp = (const ulonglong2*)(cur + b * NH + k0);
            ull a0 = 0ull, a1 = 0ull;
#pragma unroll
            for (int c = 0; c < 16; ++c) {
                ulonglong2 hv = hp[c];
                FFMA2(a0, w2[2 * c],     hv.x, a0);
                FFMA2(a1, w2[2 * c + 1], hv.y, a1);
            }
            float2 f0 = unpack2(a0);
            float2 f1 = unpack2(a1);
            accs[b] = (f0.x + f0.y) + (f1.x + f1.y);
        }
#pragma unroll
        for (int b = 0; b < 4; ++b)
            part[ks * 256 + b * 64 + jj] = accs[b];
        __syncthreads();

        // Reduce across 8 k-slices, tanh, store out + gather chunk.
        if (warp < 8) {
            float s = 0.f;
#pragma unroll
            for (int w = 0; w < 8; ++w)
                s += part[w * 256 + rb * 64 + rjl];
            const float hv = tanhf(s + pre);
            const int   bo = b0 + rb;
            hseq[((size_t)t * NB + bo) * NH + j0 + rjl] = hv;
            if (t == T_SEQ - 1 && hlast) hlast[(size_t)bo * NH + j0 + rjl] = hv;
            hx[rb * 64 + rjl] = hv;
        }
        __syncthreads();

        // Distribute our [4 x 64] chunk into every rank's NEXT buffer.
        {
            float4 v = *(const float4*)&hx[xidx * 4];
            unsigned loc = (unsigned)__cvta_generic_to_shared(
                &hbuf[(t + 1) & 1][xb * NH + j0 + xc4 * 4]);
            unsigned dst;
            asm("mapa.shared::cluster.u32 %0, %1, %2;"
                : "=r"(dst) : "r"(loc), "r"(dst_rank));
            asm volatile("st.shared::cluster.v4.b32 [%0], {%1,%2,%3,%4};"
                         :: "r"(dst), "f"(v.x), "f"(v.y), "f"(v.z), "f"(v.w)
                         : "memory");
        }

        // Cluster barrier (arrive has release, wait has acquire semantics).
        asm volatile("barrier.cluster.arrive.aligned;" ::: "memory");
        // Prefetch next step's pre-activation while peers drain/arrive.
        if (warp < 8 && t + 1 < T_SEQ)
            pre = __ldg(g_pre + ((size_t)(t + 1) * NB + (b0 + rb)) * NH + j0 + rjl);
        asm volatile("barrier.cluster.wait.aligned;" ::: "memory");
    }
}

// ---------------------------------------------------------------------------
extern "C" void kernel_launch(void* const* d_in, const int* in_sizes, int n_in,
                              void* d_out, int out_size)
{
    const float* x   = (const float*)d_in[0];
    const float* h0  = (const float*)d_in[1];
    const float* Wih = (const float*)d_in[2];
    const float* Whh = (const float*)d_in[3];
    const float* bih = (const float*)d_in[4];
    const float* bhh = (const float*)d_in[5];
    float* out = (float*)d_out;

    float* hlast = nullptr;
    if (out_size >= (int)((size_t)T_SEQ * NB * NH + NB * NH))
        hlast = out + (size_t)T_SEQ * NB * NH;

    dim3 grid(NH / BN, (T_SEQ * NB) / BM);   // (8, 256)
    gemm_xw<<<grid, 256>>>(x, Wih, bih, bhh);

    rnn_recur<<<128, RT>>>(h0, Whh, out, hlast);
}